// round 2
// baseline (speedup 1.0000x reference)
#include <cuda_runtime.h>
#include <cstdint>

#define D_FEAT 64
#define MAX_NODES 50000

// Scratch for the per-node MLP output y = relu(x @ W + b).
static __device__ float g_y[(size_t)MAX_NODES * D_FEAT];
// 1 if edge_index is int64, 0 if int32. Recomputed every call (deterministic).
static __device__ int g_is64;

// ---------------------------------------------------------------------------
// Detect index dtype: for int64 values < 2^31, every odd 32-bit word is 0.
// ---------------------------------------------------------------------------
__global__ void detect_kernel(const int* __restrict__ ei_words) {
    __shared__ int any_nonzero;
    if (threadIdx.x == 0) any_nonzero = 0;
    __syncthreads();
    // inspect odd words of the first 256 pairs
    if (ei_words[2 * threadIdx.x + 1] != 0) atomicOr(&any_nonzero, 1);
    __syncthreads();
    if (threadIdx.x == 0) g_is64 = any_nonzero ? 0 : 1;
}

// ---------------------------------------------------------------------------
// Zero the output buffer (harness poisons it to 0xAA).
// ---------------------------------------------------------------------------
__global__ void zero_kernel(float4* __restrict__ out, int n4) {
    int i = blockIdx.x * blockDim.x + threadIdx.x;
    if (i < n4) out[i] = make_float4(0.f, 0.f, 0.f, 0.f);
}

// ---------------------------------------------------------------------------
// Per-node MLP: y[r][c] = relu(sum_k x[r][k] * W[k][c] + b[c])
// 256 threads / 64 rows per block; W + padded x tile in shared.
// ---------------------------------------------------------------------------
__global__ __launch_bounds__(256) void mlp_kernel(const float* __restrict__ x,
                                                  const float* __restrict__ W,
                                                  const float* __restrict__ b,
                                                  int n) {
    __shared__ float sW[64 * 64];     // [k][c]
    __shared__ float sx[64 * 68];     // [r][k], stride 68 kills bank conflicts

    const int tid  = threadIdx.x;
    const int row0 = blockIdx.x * 64;

    {
        const float4* W4  = (const float4*)W;
        float4*       sW4 = (float4*)sW;
#pragma unroll
        for (int i = 0; i < 4; i++) sW4[tid + 256 * i] = W4[tid + 256 * i];
    }
    {
#pragma unroll
        for (int i = 0; i < 4; i++) {
            int idx = tid + 256 * i;      // 0..1023
            int r   = idx >> 4;
            int kk  = idx & 15;
            float4 v = make_float4(0.f, 0.f, 0.f, 0.f);
            if (row0 + r < n)
                v = ((const float4*)(x + (size_t)(row0 + r) * D_FEAT))[kk];
            *(float4*)&sx[r * 68 + kk * 4] = v;
        }
    }
    __syncthreads();

    const int c4 = tid & 15;
    const int r0 = tid >> 4;

    float4 acc[4];
#pragma unroll
    for (int j = 0; j < 4; j++) acc[j] = make_float4(0.f, 0.f, 0.f, 0.f);

#pragma unroll 8
    for (int k = 0; k < 64; k++) {
        float4 w = *(const float4*)&sW[k * 64 + c4 * 4];
#pragma unroll
        for (int j = 0; j < 4; j++) {
            float xv = sx[(r0 + 16 * j) * 68 + k];
            acc[j].x += xv * w.x;
            acc[j].y += xv * w.y;
            acc[j].z += xv * w.z;
            acc[j].w += xv * w.w;
        }
    }

    float4 bb = ((const float4*)b)[c4];
#pragma unroll
    for (int j = 0; j < 4; j++) {
        int r = row0 + r0 + 16 * j;
        if (r < n) {
            float4 v;
            v.x = fmaxf(acc[j].x + bb.x, 0.f);
            v.y = fmaxf(acc[j].y + bb.y, 0.f);
            v.z = fmaxf(acc[j].z + bb.z, 0.f);
            v.w = fmaxf(acc[j].w + bb.w, 0.f);
            ((float4*)(g_y + (size_t)r * D_FEAT))[c4] = v;
        }
    }
}

// ---------------------------------------------------------------------------
// Edge scatter: out[dst[e]] += y[src[e]]   (16 threads per edge, float4 each)
// Both buffers are L2-resident; vectorized red quarters atomic op count.
// ---------------------------------------------------------------------------
__global__ __launch_bounds__(256) void scatter_kernel(const void* __restrict__ ei,
                                                      float* __restrict__ out,
                                                      int E) {
    int t = blockIdx.x * blockDim.x + threadIdx.x;
    int e = t >> 4;
    if (e >= E) return;
    int lane = t & 15;

    int src, dst;
    if (g_is64) {
        const long long* p = (const long long*)ei;
        src = (int)__ldg(&p[e]);
        dst = (int)__ldg(&p[(size_t)E + e]);
    } else {
        const int* p = (const int*)ei;
        src = __ldg(&p[e]);
        dst = __ldg(&p[(size_t)E + e]);
    }

    float4 v = __ldg((const float4*)(g_y + (size_t)src * D_FEAT) + lane);

    float* o = out + (size_t)dst * D_FEAT + (lane << 2);
    asm volatile("red.global.add.v4.f32 [%0], {%1, %2, %3, %4};"
                 :: "l"(o), "f"(v.x), "f"(v.y), "f"(v.z), "f"(v.w)
                 : "memory");
}

// ---------------------------------------------------------------------------
// Inputs (metadata order): x [n*64 f32], edge_index [2*E int], W [64*64 f32],
//                          b [64 f32].  Output: [n*64 f32].
// ---------------------------------------------------------------------------
extern "C" void kernel_launch(void* const* d_in, const int* in_sizes, int n_in,
                              void* d_out, int out_size) {
    const float* x   = (const float*)d_in[0];
    const void*  ei  = d_in[1];
    const float* W   = (const float*)d_in[2];
    const float* b   = (const float*)d_in[3];
    float*       out = (float*)d_out;

    int n = in_sizes[0] / D_FEAT;
    int E = in_sizes[1] / 2;

    detect_kernel<<<1, 256>>>((const int*)ei);

    int n4 = out_size / 4;
    zero_kernel<<<(n4 + 255) / 256, 256>>>((float4*)d_out, n4);
    mlp_kernel<<<(n + 63) / 64, 256>>>(x, W, b, n);

    long long total = (long long)E * 16;
    int grid = (int)((total + 255) / 256);
    scatter_kernel<<<grid, 256>>>(ei, out, E);
}